// round 9
// baseline (speedup 1.0000x reference)
#include <cuda_runtime.h>
#include <cstdint>

#define TMAX 1280

__device__ int g_lab[TMAX];        // fallback path only
__device__ float4 g_txyxy[TMAX];   // fallback path only
__device__ float2 g_tal[TMAX];     // fallback path only

__device__ __forceinline__ float frcp(float x) {
    float r;
    asm("rcp.approx.f32 %0, %1;" : "=f"(r) : "f"(x));
    return r;
}

// Fallback-path setup: label normalize + target xyxy/area precompute.
__global__ void setup_kernel(const float4* __restrict__ tboxes,
                             const int* __restrict__ lraw, int m) {
    __shared__ int is64;
    if (threadIdx.x == 0) is64 = 1;
    __syncthreads();
    for (int t = threadIdx.x; t < m / 2; t += blockDim.x)
        if (lraw[2 * t + 1] != 0) is64 = 0;
    __syncthreads();
    int f = is64;
    for (int j = threadIdx.x; j < m; j += blockDim.x) {
        int lab = f ? lraw[2 * j] : lraw[j];
        g_lab[j] = lab;
        float4 b = tboxes[j];
        float hw = 0.5f * b.z, hh = 0.5f * b.w;
        float4 t;
        t.x = b.x - hw; t.y = b.y - hh;
        t.z = b.x + hw; t.w = b.y + hh;
        g_txyxy[j] = t;
        float2 al;
        al.x = (t.z - t.x) * (t.w - t.y);
        al.y = __int_as_float(lab);
        g_tal[j] = al;
    }
}

// ---------------------------------------------------------------------------
// Fast-path tile body: 4 rows x 20 column steps per thread (lean R7 math).
// Templated on label stride (SH=1: int64 source, SH=0: int32).
// ---------------------------------------------------------------------------
template <int SH>
__device__ __forceinline__ void cost_tile4(
    const float* __restrict__ sp,        // scores + row0*C
    float* __restrict__ op,              // out + row0*M + tx
    const float4* __restrict__ tb,       // tboxes + tx
    const int* __restrict__ lp,          // lraw + (tx << SH)
    const float qcx[4], const float qcy[4],
    const float qwz[4], const float qwh[4],
    const float qx0[4], const float qy0[4],
    const float qx1[4], const float qy1[4])
{
    constexpr int C = 91;
    constexpr int M = 1280;

#pragma unroll 5
    for (int jj = 0; jj < 20; jj++) {
        float4 b = __ldg(tb + jj * 64);          // target cxcywh
        int lab = __ldg(lp + ((jj * 64) << SH)); // immediate-offset label
        float hw = 0.5f * b.z, hh = 0.5f * b.w;
        float tx0 = b.x - hw, ty0 = b.y - hh;
        float tx1 = b.x + hw, ty1 = b.y + hh;
        float ta = b.z * b.w;
        const float* sa = sp + lab;

        float scv[4];
#pragma unroll
        for (int k = 0; k < 4; k++) scv[k] = __ldg(sa + k * C);

#pragma unroll
        for (int k = 0; k < 4; k++) {
            // L1 on raw cxcywh (exact vs reference; abs folds into operands)
            float ux = qcx[k] - b.x, uy = qcy[k] - b.y;
            float vx = qwz[k] - b.z, vy = qwh[k] - b.w;
            float l1 = (fabsf(ux) + fabsf(uy)) + (fabsf(vx) + fabsf(vy));

            // signed per-dim overlap, reused for intersection and enclosure
            float ox = fminf(qx1[k], tx1) - fmaxf(qx0[k], tx0);
            float oy = fminf(qy1[k], ty1) - fmaxf(qy0[k], ty0);
            float iw = fmaxf(ox, 0.0f), ih = fmaxf(oy, 0.0f);
            float inter = iw * ih;

            // enclosing span = w + w' - signed_overlap
            float ew = (qwz[k] + b.z) - ox;
            float eh = (qwh[k] + b.w) - oy;
            float ae = ew * eh;

            float uni = fmaf(qwz[k], qwh[k], ta) - inter;

            // cost = 5*l1 + (2 - sc) - 2*(inter/uni + uni/ae)
            float s = fmaf(uni, frcp(ae), inter * frcp(uni));
            float c = fmaf(5.0f, l1, 2.0f - scv[k]);
            c = fmaf(-2.0f, s, c);

            op[k * M + jj * 64] = c;
        }
    }
}

// ---------------------------------------------------------------------------
// Fast path: C=91, M=1280, rows % 8 == 0. Single launch.
// 128-thr block = 2 groups x (4 rows x 64 lanes) = 8 rows; grid = rows/8.
// launch_bounds(128,8): 64-reg cap, 8 blocks/SM -> 151552 resident threads
// vs 153600 total -> 1.013 waves (kills the 1.62-wave quantization of R7).
// ---------------------------------------------------------------------------
__global__ void __launch_bounds__(128, 8)
cost_kernel_fast(const float* __restrict__ scores,
                 const float4* __restrict__ boxes,
                 const int* __restrict__ lraw,
                 const float4* __restrict__ tboxes,
                 float* __restrict__ out) {
    constexpr int C = 91;
    constexpr int M = 1280;

    int tid = threadIdx.x;
    int tx = tid & 63;
    int ty = tid >> 6;
    int row0 = blockIdx.x * 8 + ty * 4;

    // Label-width probe: int64 labels (<2^31) have all-zero high words.
    __shared__ int s_is64;
    if (tid == 0) s_is64 = 1;
    __syncthreads();
    {
        int any = 0;
#pragma unroll 1
        for (int t = tid; t < M / 2; t += 128)
            any |= lraw[2 * t + 1];
        if (any != 0) s_is64 = 0;
    }

    float qcx[4], qcy[4], qwz[4], qwh[4];
    float qx0[4], qy0[4], qx1[4], qy1[4];
#pragma unroll
    for (int k = 0; k < 4; k++) {
        float4 bb = __ldg(boxes + row0 + k);
        qcx[k] = bb.x; qcy[k] = bb.y; qwz[k] = bb.z; qwh[k] = bb.w;
        float hw = 0.5f * bb.z, hh = 0.5f * bb.w;
        qx0[k] = bb.x - hw; qy0[k] = bb.y - hh;
        qx1[k] = bb.x + hw; qy1[k] = bb.y + hh;
    }
    __syncthreads();

    const float* sp = scores + row0 * C;
    float* op = out + (size_t)row0 * M + tx;
    const float4* tb = tboxes + tx;

    if (s_is64)
        cost_tile4<1>(sp, op, tb, lraw + 2 * tx,
                      qcx, qcy, qwz, qwh, qx0, qy0, qx1, qy1);
    else
        cost_tile4<0>(sp, op, tb, lraw + tx,
                      qcx, qcy, qwz, qwh, qx0, qy0, qx1, qy1);
}

// ---------------------------------------------------------------------------
// Generic fallback for unexpected shapes.
// ---------------------------------------------------------------------------
__global__ void __launch_bounds__(256)
cost_kernel(const float* __restrict__ scores,
            const float4* __restrict__ boxes,
            const float4* __restrict__ tboxes,
            float* __restrict__ out,
            int rows, int C, int m) {
    int tid = threadIdx.x;
    int tx = tid & 63;
    int ty = tid >> 6;
    int row0 = blockIdx.x * 16 + ty * 4;

    float qcx[4], qcy[4], qw[4], qh[4];
    float qx0[4], qy0[4], qx1[4], qy1[4], qa[4];
    const float* srow[4];
    float* orow[4];

#pragma unroll
    for (int k = 0; k < 4; k++) {
        int r = row0 + k;
        if (r > rows - 1) r = rows - 1;
        float4 bb = __ldg(boxes + r);
        qcx[k] = bb.x; qcy[k] = bb.y; qw[k] = bb.z; qh[k] = bb.w;
        float hw = 0.5f * bb.z, hh = 0.5f * bb.w;
        qx0[k] = bb.x - hw; qy0[k] = bb.y - hh;
        qx1[k] = bb.x + hw; qy1[k] = bb.y + hh;
        qa[k] = (qx1[k] - qx0[k]) * (qy1[k] - qy0[k]);
        srow[k] = scores + (size_t)r * C;
        orow[k] = out + (size_t)r * m + tx;
    }

    int nj = (m + 63) >> 6;
    for (int jj = 0; jj < nj; jj++) {
        int j = tx + (jj << 6);
        if (j >= m) break;
        float4 t  = __ldg(g_txyxy + j);
        float4 tc = __ldg(tboxes + j);
        float2 al = __ldg(g_tal + j);
        float ta = al.x;
        int lab = __float_as_int(al.y);

#pragma unroll
        for (int k = 0; k < 4; k++) {
            float sc = __ldg(srow[k] + lab);
            float l1 = fabsf(qcx[k] - tc.x) + fabsf(qcy[k] - tc.y)
                     + fabsf(qw[k] - tc.z) + fabsf(qh[k] - tc.w);
            float ltx = fmaxf(qx0[k], t.x), lty = fmaxf(qy0[k], t.y);
            float rbx = fminf(qx1[k], t.z), rby = fminf(qy1[k], t.w);
            float iw = fmaxf(rbx - ltx, 0.0f), ih = fmaxf(rby - lty, 0.0f);
            float inter = iw * ih;
            float uni = qa[k] + ta - inter;
            float ex0 = fminf(qx0[k], t.x), ey0 = fminf(qy0[k], t.y);
            float ex1 = fmaxf(qx1[k], t.z), ey1 = fmaxf(qy1[k], t.w);
            float ae = (ex1 - ex0) * (ey1 - ey0);
            float s = fmaf(uni, frcp(ae), inter * frcp(uni));
            float c = fmaf(5.0f, l1, 2.0f - sc);
            c = fmaf(-2.0f, s, c);
            orow[k][(size_t)(jj << 6)] = c;
        }
    }
}

extern "C" void kernel_launch(void* const* d_in, const int* in_sizes, int n_in,
                              void* d_out, int out_size) {
    const float* scores  = (const float*)d_in[0];
    const float4* boxes  = (const float4*)d_in[1];
    const int*   labraw  = (const int*)d_in[2];
    const float4* tboxes = (const float4*)d_in[3];
    float* out = (float*)d_out;

    int rows = in_sizes[1] / 4;      // b*n = 9600
    int m    = in_sizes[3] / 4;      // 1280
    int C    = in_sizes[0] / rows;   // 91

    if (C == 91 && m == 1280 && (rows % 8) == 0) {
        cost_kernel_fast<<<rows / 8, 128>>>(scores, boxes, labraw, tboxes, out);
    } else {
        setup_kernel<<<1, 512>>>(tboxes, labraw, m);
        int blocks = (rows + 15) / 16;
        cost_kernel<<<blocks, 256>>>(scores, boxes, tboxes, out, rows, C, m);
    }
}

// round 10
// speedup vs baseline: 1.0656x; 1.0656x over previous
#include <cuda_runtime.h>
#include <cstdint>

#define TMAX 1280

__device__ int g_lab[TMAX];        // fallback path only
__device__ float4 g_txyxy[TMAX];   // fallback path only
__device__ float2 g_tal[TMAX];     // fallback path only

__device__ __forceinline__ float frcp(float x) {
    float r;
    asm("rcp.approx.f32 %0, %1;" : "=f"(r) : "f"(x));
    return r;
}

// Fallback-path setup: label normalize + target xyxy/area precompute.
__global__ void setup_kernel(const float4* __restrict__ tboxes,
                             const int* __restrict__ lraw, int m) {
    __shared__ int is64;
    if (threadIdx.x == 0) is64 = 1;
    __syncthreads();
    for (int t = threadIdx.x; t < m / 2; t += blockDim.x)
        if (lraw[2 * t + 1] != 0) is64 = 0;
    __syncthreads();
    int f = is64;
    for (int j = threadIdx.x; j < m; j += blockDim.x) {
        int lab = f ? lraw[2 * j] : lraw[j];
        g_lab[j] = lab;
        float4 b = tboxes[j];
        float hw = 0.5f * b.z, hh = 0.5f * b.w;
        float4 t;
        t.x = b.x - hw; t.y = b.y - hh;
        t.z = b.x + hw; t.w = b.y + hh;
        g_txyxy[j] = t;
        float2 al;
        al.x = (t.z - t.x) * (t.w - t.y);
        al.y = __int_as_float(lab);
        g_tal[j] = al;
    }
}

// ---------------------------------------------------------------------------
// Fast-path tile body: 2 rows x 40 column steps per thread, 32-lane slices.
// Identical per-pair math to the proven 48-reg R7 body; only the lane
// geometry changed (32 lanes x 40 steps instead of 64 x 20), which halves
// the launched thread count without touching per-thread register state.
// Templated on label stride (SH=1: int64 source, SH=0: int32).
// ---------------------------------------------------------------------------
template <int SH>
__device__ __forceinline__ void cost_tile2(
    const float* __restrict__ sp,        // scores + row0*C
    float* __restrict__ op,              // out + row0*M + tx
    const float4* __restrict__ tb,       // tboxes + tx
    const int* __restrict__ lp,          // lraw + (tx << SH)
    const float qcx[2], const float qcy[2],
    const float qwz[2], const float qwh[2],
    const float qx0[2], const float qy0[2],
    const float qx1[2], const float qy1[2])
{
    constexpr int C = 91;
    constexpr int M = 1280;

#pragma unroll 10
    for (int jj = 0; jj < 40; jj++) {
        float4 b = __ldg(tb + jj * 32);          // target cxcywh
        int lab = __ldg(lp + ((jj * 32) << SH)); // immediate-offset label
        float hw = 0.5f * b.z, hh = 0.5f * b.w;
        float tx0 = b.x - hw, ty0 = b.y - hh;
        float tx1 = b.x + hw, ty1 = b.y + hh;
        float ta = b.z * b.w;
        const float* sa = sp + lab;

        float scv[2];
#pragma unroll
        for (int k = 0; k < 2; k++) scv[k] = __ldg(sa + k * C);

#pragma unroll
        for (int k = 0; k < 2; k++) {
            // L1 on raw cxcywh (exact vs reference; abs folds into operands)
            float ux = qcx[k] - b.x, uy = qcy[k] - b.y;
            float vx = qwz[k] - b.z, vy = qwh[k] - b.w;
            float l1 = (fabsf(ux) + fabsf(uy)) + (fabsf(vx) + fabsf(vy));

            // signed per-dim overlap, reused for intersection and enclosure
            float ox = fminf(qx1[k], tx1) - fmaxf(qx0[k], tx0);
            float oy = fminf(qy1[k], ty1) - fmaxf(qy0[k], ty0);
            float iw = fmaxf(ox, 0.0f), ih = fmaxf(oy, 0.0f);
            float inter = iw * ih;

            // enclosing span = w + w' - signed_overlap
            float ew = (qwz[k] + b.z) - ox;
            float eh = (qwh[k] + b.w) - oy;
            float ae = ew * eh;

            float uni = fmaf(qwz[k], qwh[k], ta) - inter;

            // cost = 5*l1 + (2 - sc) - 2*(inter/uni + uni/ae)
            float s = fmaf(uni, frcp(ae), inter * frcp(uni));
            float c = fmaf(5.0f, l1, 2.0f - scv[k]);
            c = fmaf(-2.0f, s, c);

            op[k * M + jj * 32] = c;
        }
    }
}

// ---------------------------------------------------------------------------
// Fast path: C=91, M=1280, rows % 8 == 0. Single launch.
// 128-thr block = 4 groups x (2 rows x 32 lanes) = 8 rows; grid = rows/8.
// Total threads = 153,600 at ~48 regs = 7.4M regs < 9.7M on-chip -> ONE wave
// (R7's 64-lane version needed 307,200 threads -> 1.62 waves).
// launch_bounds(128,10) -> 51-reg cap (spill-free for this body per R7),
// 10 blocks/SM capacity; 1200 blocks -> ~8.1 blocks/SM, makespan ~1.11x.
// ---------------------------------------------------------------------------
__global__ void __launch_bounds__(128, 10)
cost_kernel_fast(const float* __restrict__ scores,
                 const float4* __restrict__ boxes,
                 const int* __restrict__ lraw,
                 const float4* __restrict__ tboxes,
                 float* __restrict__ out) {
    constexpr int C = 91;
    constexpr int M = 1280;

    int tid = threadIdx.x;
    int tx = tid & 31;
    int ty = tid >> 5;
    int row0 = blockIdx.x * 8 + ty * 2;

    // Label-width probe: int64 labels (<2^31) have all-zero high words.
    __shared__ int s_is64;
    if (tid == 0) s_is64 = 1;
    __syncthreads();
    {
        int any = 0;
#pragma unroll 1
        for (int t = tid; t < M / 2; t += 128)
            any |= lraw[2 * t + 1];
        if (any != 0) s_is64 = 0;
    }

    float qcx[2], qcy[2], qwz[2], qwh[2];
    float qx0[2], qy0[2], qx1[2], qy1[2];
#pragma unroll
    for (int k = 0; k < 2; k++) {
        float4 bb = __ldg(boxes + row0 + k);
        qcx[k] = bb.x; qcy[k] = bb.y; qwz[k] = bb.z; qwh[k] = bb.w;
        float hw = 0.5f * bb.z, hh = 0.5f * bb.w;
        qx0[k] = bb.x - hw; qy0[k] = bb.y - hh;
        qx1[k] = bb.x + hw; qy1[k] = bb.y + hh;
    }
    __syncthreads();

    const float* sp = scores + row0 * C;
    float* op = out + (size_t)row0 * M + tx;
    const float4* tb = tboxes + tx;

    if (s_is64)
        cost_tile2<1>(sp, op, tb, lraw + 2 * tx,
                      qcx, qcy, qwz, qwh, qx0, qy0, qx1, qy1);
    else
        cost_tile2<0>(sp, op, tb, lraw + tx,
                      qcx, qcy, qwz, qwh, qx0, qy0, qx1, qy1);
}

// ---------------------------------------------------------------------------
// Generic fallback for unexpected shapes.
// ---------------------------------------------------------------------------
__global__ void __launch_bounds__(256)
cost_kernel(const float* __restrict__ scores,
            const float4* __restrict__ boxes,
            const float4* __restrict__ tboxes,
            float* __restrict__ out,
            int rows, int C, int m) {
    int tid = threadIdx.x;
    int tx = tid & 63;
    int ty = tid >> 6;
    int row0 = blockIdx.x * 16 + ty * 4;

    float qcx[4], qcy[4], qw[4], qh[4];
    float qx0[4], qy0[4], qx1[4], qy1[4], qa[4];
    const float* srow[4];
    float* orow[4];

#pragma unroll
    for (int k = 0; k < 4; k++) {
        int r = row0 + k;
        if (r > rows - 1) r = rows - 1;
        float4 bb = __ldg(boxes + r);
        qcx[k] = bb.x; qcy[k] = bb.y; qw[k] = bb.z; qh[k] = bb.w;
        float hw = 0.5f * bb.z, hh = 0.5f * bb.w;
        qx0[k] = bb.x - hw; qy0[k] = bb.y - hh;
        qx1[k] = bb.x + hw; qy1[k] = bb.y + hh;
        qa[k] = (qx1[k] - qx0[k]) * (qy1[k] - qy0[k]);
        srow[k] = scores + (size_t)r * C;
        orow[k] = out + (size_t)r * m + tx;
    }

    int nj = (m + 63) >> 6;
    for (int jj = 0; jj < nj; jj++) {
        int j = tx + (jj << 6);
        if (j >= m) break;
        float4 t  = __ldg(g_txyxy + j);
        float4 tc = __ldg(tboxes + j);
        float2 al = __ldg(g_tal + j);
        float ta = al.x;
        int lab = __float_as_int(al.y);

#pragma unroll
        for (int k = 0; k < 4; k++) {
            float sc = __ldg(srow[k] + lab);
            float l1 = fabsf(qcx[k] - tc.x) + fabsf(qcy[k] - tc.y)
                     + fabsf(qw[k] - tc.z) + fabsf(qh[k] - tc.w);
            float ltx = fmaxf(qx0[k], t.x), lty = fmaxf(qy0[k], t.y);
            float rbx = fminf(qx1[k], t.z), rby = fminf(qy1[k], t.w);
            float iw = fmaxf(rbx - ltx, 0.0f), ih = fmaxf(rby - lty, 0.0f);
            float inter = iw * ih;
            float uni = qa[k] + ta - inter;
            float ex0 = fminf(qx0[k], t.x), ey0 = fminf(qy0[k], t.y);
            float ex1 = fmaxf(qx1[k], t.z), ey1 = fmaxf(qy1[k], t.w);
            float ae = (ex1 - ex0) * (ey1 - ey0);
            float s = fmaf(uni, frcp(ae), inter * frcp(uni));
            float c = fmaf(5.0f, l1, 2.0f - sc);
            c = fmaf(-2.0f, s, c);
            orow[k][(size_t)(jj << 6)] = c;
        }
    }
}

extern "C" void kernel_launch(void* const* d_in, const int* in_sizes, int n_in,
                              void* d_out, int out_size) {
    const float* scores  = (const float*)d_in[0];
    const float4* boxes  = (const float4*)d_in[1];
    const int*   labraw  = (const int*)d_in[2];
    const float4* tboxes = (const float4*)d_in[3];
    float* out = (float*)d_out;

    int rows = in_sizes[1] / 4;      // b*n = 9600
    int m    = in_sizes[3] / 4;      // 1280
    int C    = in_sizes[0] / rows;   // 91

    if (C == 91 && m == 1280 && (rows % 8) == 0) {
        cost_kernel_fast<<<rows / 8, 128>>>(scores, boxes, labraw, tboxes, out);
    } else {
        setup_kernel<<<1, 512>>>(tboxes, labraw, m);
        int blocks = (rows + 15) / 16;
        cost_kernel<<<blocks, 256>>>(scores, boxes, tboxes, out, rows, C, m);
    }
}

// round 12
// speedup vs baseline: 1.1302x; 1.0607x over previous
#include <cuda_runtime.h>
#include <cstdint>

#define TMAX 1280

__device__ int g_lab[TMAX];        // fallback path only
__device__ float4 g_txyxy[TMAX];   // fallback path only
__device__ float2 g_tal[TMAX];     // fallback path only

__device__ __forceinline__ float frcp(float x) {
    float r;
    asm("rcp.approx.f32 %0, %1;" : "=f"(r) : "f"(x));
    return r;
}

// Fallback-path setup: label normalize + target xyxy/area precompute.
__global__ void setup_kernel(const float4* __restrict__ tboxes,
                             const int* __restrict__ lraw, int m) {
    __shared__ int is64;
    if (threadIdx.x == 0) is64 = 1;
    __syncthreads();
    for (int t = threadIdx.x; t < m / 2; t += blockDim.x)
        if (lraw[2 * t + 1] != 0) is64 = 0;
    __syncthreads();
    int f = is64;
    for (int j = threadIdx.x; j < m; j += blockDim.x) {
        int lab = f ? lraw[2 * j] : lraw[j];
        g_lab[j] = lab;
        float4 b = tboxes[j];
        float hw = 0.5f * b.z, hh = 0.5f * b.w;
        float4 t;
        t.x = b.x - hw; t.y = b.y - hh;
        t.z = b.x + hw; t.w = b.y + hh;
        g_txyxy[j] = t;
        float2 al;
        al.x = (t.z - t.x) * (t.w - t.y);
        al.y = __int_as_float(lab);
        g_tal[j] = al;
    }
}

// ---------------------------------------------------------------------------
// Fast-path tile body: 2 rows x 20 column steps per thread (R7 geometry).
// Score lookups come from SMEM-staged rows (ssc), not global gathers.
// Templated on label stride (SH=1: int64 source, SH=0: int32).
// ---------------------------------------------------------------------------
#define SC_PAD 93   // smem row stride in floats (93 % 32 = 29 -> rows spread banks)

template <int SH>
__device__ __forceinline__ void cost_tile2(
    const float* __restrict__ ssc,       // smem score base for this 2-row group
    float* __restrict__ op,              // out + row0*M + tx
    const float4* __restrict__ tb,       // tboxes + tx
    const int* __restrict__ lp,          // lraw + (tx << SH)
    const float qcx[2], const float qcy[2],
    const float qwz[2], const float qwh[2],
    const float qx0[2], const float qy0[2],
    const float qx1[2], const float qy1[2])
{
    constexpr int M = 1280;

#pragma unroll 10
    for (int jj = 0; jj < 20; jj++) {
        float4 b = __ldg(tb + jj * 64);          // target cxcywh
        int lab = __ldg(lp + ((jj * 64) << SH)); // immediate-offset label
        float hw = 0.5f * b.z, hh = 0.5f * b.w;
        float tx0 = b.x - hw, ty0 = b.y - hh;
        float tx1 = b.x + hw, ty1 = b.y + hh;
        float ta = b.z * b.w;

        float scv[2];
#pragma unroll
        for (int k = 0; k < 2; k++) scv[k] = ssc[k * SC_PAD + lab];  // LDS gather

#pragma unroll
        for (int k = 0; k < 2; k++) {
            // L1 on raw cxcywh (exact vs reference; abs folds into operands)
            float ux = qcx[k] - b.x, uy = qcy[k] - b.y;
            float vx = qwz[k] - b.z, vy = qwh[k] - b.w;
            float l1 = (fabsf(ux) + fabsf(uy)) + (fabsf(vx) + fabsf(vy));

            // signed per-dim overlap, reused for intersection and enclosure
            float ox = fminf(qx1[k], tx1) - fmaxf(qx0[k], tx0);
            float oy = fminf(qy1[k], ty1) - fmaxf(qy0[k], ty0);
            float iw = fmaxf(ox, 0.0f), ih = fmaxf(oy, 0.0f);
            float inter = iw * ih;

            // enclosing span = w + w' - signed_overlap
            float ew = (qwz[k] + b.z) - ox;
            float eh = (qwh[k] + b.w) - oy;
            float ae = ew * eh;

            float uni = fmaf(qwz[k], qwh[k], ta) - inter;

            // cost = 5*l1 + (2 - sc) - 2*(inter/uni + uni/ae)
            float s = fmaf(uni, frcp(ae), inter * frcp(uni));
            float c = fmaf(5.0f, l1, 2.0f - scv[k]);
            c = fmaf(-2.0f, s, c);

            op[k * M + jj * 64] = c;
        }
    }
}

// ---------------------------------------------------------------------------
// Fast path: C=91, M=1280, rows % 8 == 0. Single launch. R7 geometry:
// 256-thr block = 4 groups x (2 rows x 64 lanes) = 8 rows; grid = rows/8;
// launch_bounds(256,5) -> 51-reg cap (compiled to 48 in R7), 40 warps/SM.
// NEW vs R7: block stages its 8 score rows into SMEM; the per-pair score
// gather becomes an LDS (bank-broadcast on equal labels) instead of a
// scattered LDG touching ~10 sectors.
// ---------------------------------------------------------------------------
__global__ void __launch_bounds__(256, 5)
cost_kernel_fast(const float* __restrict__ scores,
                 const float4* __restrict__ boxes,
                 const int* __restrict__ lraw,
                 const float4* __restrict__ tboxes,
                 float* __restrict__ out) {
    constexpr int C = 91;
    constexpr int M = 1280;

    __shared__ float s_sc[8 * SC_PAD];
    __shared__ int s_is64;

    int tid = threadIdx.x;
    int tx = tid & 63;
    int ty = tid >> 6;
    int row0 = blockIdx.x * 8 + ty * 2;

    if (tid == 0) s_is64 = 1;
    __syncthreads();

    // Label-width probe: int64 labels (<2^31) have all-zero high words.
    {
        int any = 0;
#pragma unroll 1
        for (int t = tid; t < M / 2; t += 256)
            any |= lraw[2 * t + 1];
        if (any != 0) s_is64 = 0;
    }

    // Stage this block's 8 score rows into SMEM (warp w loads row w).
    {
        int w = tid >> 5, l = tid & 31;
        const float* src = scores + (size_t)(blockIdx.x * 8 + w) * C;
#pragma unroll
        for (int c = l; c < C; c += 32)
            s_sc[w * SC_PAD + c] = __ldg(src + c);
    }

    float qcx[2], qcy[2], qwz[2], qwh[2];
    float qx0[2], qy0[2], qx1[2], qy1[2];
#pragma unroll
    for (int k = 0; k < 2; k++) {
        float4 bb = __ldg(boxes + row0 + k);
        qcx[k] = bb.x; qcy[k] = bb.y; qwz[k] = bb.z; qwh[k] = bb.w;
        float hw = 0.5f * bb.z, hh = 0.5f * bb.w;
        qx0[k] = bb.x - hw; qy0[k] = bb.y - hh;
        qx1[k] = bb.x + hw; qy1[k] = bb.y + hh;
    }
    __syncthreads();

    const float* ssc = &s_sc[ty * 2 * SC_PAD];
    float* op = out + (size_t)row0 * M + tx;
    const float4* tb = tboxes + tx;

    if (s_is64)
        cost_tile2<1>(ssc, op, tb, lraw + 2 * tx,
                      qcx, qcy, qwz, qwh, qx0, qy0, qx1, qy1);
    else
        cost_tile2<0>(ssc, op, tb, lraw + tx,
                      qcx, qcy, qwz, qwh, qx0, qy0, qx1, qy1);
}

// ---------------------------------------------------------------------------
// Generic fallback for unexpected shapes.
// ---------------------------------------------------------------------------
__global__ void __launch_bounds__(256)
cost_kernel(const float* __restrict__ scores,
            const float4* __restrict__ boxes,
            const float4* __restrict__ tboxes,
            float* __restrict__ out,
            int rows, int C, int m) {
    int tid = threadIdx.x;
    int tx = tid & 63;
    int ty = tid >> 6;
    int row0 = blockIdx.x * 16 + ty * 4;

    float qcx[4], qcy[4], qw[4], qh[4];
    float qx0[4], qy0[4], qx1[4], qy1[4], qa[4];
    const float* srow[4];
    float* orow[4];

#pragma unroll
    for (int k = 0; k < 4; k++) {
        int r = row0 + k;
        if (r > rows - 1) r = rows - 1;
        float4 bb = __ldg(boxes + r);
        qcx[k] = bb.x; qcy[k] = bb.y; qw[k] = bb.z; qh[k] = bb.w;
        float hw = 0.5f * bb.z, hh = 0.5f * bb.w;
        qx0[k] = bb.x - hw; qy0[k] = bb.y - hh;
        qx1[k] = bb.x + hw; qy1[k] = bb.y + hh;
        qa[k] = (qx1[k] - qx0[k]) * (qy1[k] - qy0[k]);
        srow[k] = scores + (size_t)r * C;
        orow[k] = out + (size_t)r * m + tx;
    }

    int nj = (m + 63) >> 6;
    for (int jj = 0; jj < nj; jj++) {
        int j = tx + (jj << 6);
        if (j >= m) break;
        float4 t  = __ldg(g_txyxy + j);
        float4 tc = __ldg(tboxes + j);
        float2 al = __ldg(g_tal + j);
        float ta = al.x;
        int lab = __float_as_int(al.y);

#pragma unroll
        for (int k = 0; k < 4; k++) {
            float sc = __ldg(srow[k] + lab);
            float l1 = fabsf(qcx[k] - tc.x) + fabsf(qcy[k] - tc.y)
                     + fabsf(qw[k] - tc.z) + fabsf(qh[k] - tc.w);
            float ltx = fmaxf(qx0[k], t.x), lty = fmaxf(qy0[k], t.y);
            float rbx = fminf(qx1[k], t.z), rby = fminf(qy1[k], t.w);
            float iw = fmaxf(rbx - ltx, 0.0f), ih = fmaxf(rby - lty, 0.0f);
            float inter = iw * ih;
            float uni = qa[k] + ta - inter;
            float ex0 = fminf(qx0[k], t.x), ey0 = fminf(qy0[k], t.y);
            float ex1 = fmaxf(qx1[k], t.z), ey1 = fmaxf(qy1[k], t.w);
            float ae = (ex1 - ex0) * (ey1 - ey0);
            float s = fmaf(uni, frcp(ae), inter * frcp(uni));
            float c = fmaf(5.0f, l1, 2.0f - sc);
            c = fmaf(-2.0f, s, c);
            orow[k][(size_t)(jj << 6)] = c;
        }
    }
}

extern "C" void kernel_launch(void* const* d_in, const int* in_sizes, int n_in,
                              void* d_out, int out_size) {
    const float* scores  = (const float*)d_in[0];
    const float4* boxes  = (const float4*)d_in[1];
    const int*   labraw  = (const int*)d_in[2];
    const float4* tboxes = (const float4*)d_in[3];
    float* out = (float*)d_out;

    int rows = in_sizes[1] / 4;      // b*n = 9600
    int m    = in_sizes[3] / 4;      // 1280
    int C    = in_sizes[0] / rows;   // 91

    if (C == 91 && m == 1280 && (rows % 8) == 0) {
        cost_kernel_fast<<<rows / 8, 256>>>(scores, boxes, labraw, tboxes, out);
    } else {
        setup_kernel<<<1, 512>>>(tboxes, labraw, m);
        int blocks = (rows + 15) / 16;
        cost_kernel<<<blocks, 256>>>(scores, boxes, tboxes, out, rows, C, m);
    }
}

// round 13
// speedup vs baseline: 1.1416x; 1.0100x over previous
#include <cuda_runtime.h>
#include <cstdint>

#define TMAX 1280

__device__ int g_lab[TMAX];        // fallback path only
__device__ float4 g_txyxy[TMAX];   // fallback path only
__device__ float2 g_tal[TMAX];     // fallback path only

__device__ __forceinline__ float frcp(float x) {
    float r;
    asm("rcp.approx.f32 %0, %1;" : "=f"(r) : "f"(x));
    return r;
}

// Packed f32x2 helpers (bit-exact per-lane .rn arithmetic).
#define PACK2(dst, lo, hi) \
    asm("mov.b64 %0, {%1, %2};" : "=l"(dst) : "r"(__float_as_uint(lo)), "r"(__float_as_uint(hi)))
#define UNPACK2(lo, hi, src) do { unsigned int _ulo, _uhi; \
    asm("mov.b64 {%0, %1}, %2;" : "=r"(_ulo), "=r"(_uhi) : "l"(src)); \
    lo = __uint_as_float(_ulo); hi = __uint_as_float(_uhi); } while (0)
#define ADDX2(dst, a, b) \
    asm("add.rn.f32x2 %0, %1, %2;" : "=l"(dst) : "l"(a), "l"(b))

// Fallback-path setup: label normalize + target xyxy/area precompute.
__global__ void setup_kernel(const float4* __restrict__ tboxes,
                             const int* __restrict__ lraw, int m) {
    __shared__ int is64;
    if (threadIdx.x == 0) is64 = 1;
    __syncthreads();
    for (int t = threadIdx.x; t < m / 2; t += blockDim.x)
        if (lraw[2 * t + 1] != 0) is64 = 0;
    __syncthreads();
    int f = is64;
    for (int j = threadIdx.x; j < m; j += blockDim.x) {
        int lab = f ? lraw[2 * j] : lraw[j];
        g_lab[j] = lab;
        float4 b = tboxes[j];
        float hw = 0.5f * b.z, hh = 0.5f * b.w;
        float4 t;
        t.x = b.x - hw; t.y = b.y - hh;
        t.z = b.x + hw; t.w = b.y + hh;
        g_txyxy[j] = t;
        float2 al;
        al.x = (t.z - t.x) * (t.w - t.y);
        al.y = __int_as_float(lab);
        g_tal[j] = al;
    }
}

// ---------------------------------------------------------------------------
// Fast-path tile body: 2 rows x 20 column steps per thread (R7/R12 geometry).
// Score values come from SMEM pre-negated (2 - score), interleaved by row so
// one LDS.64 serves both rows. L1 x/y diff via one packed f32x2 add.
// Templated on label stride (SH=1: int64 source, SH=0: int32).
// ---------------------------------------------------------------------------
template <int SH>
__device__ __forceinline__ void cost_tile2(
    const float2* __restrict__ ssc2,     // smem (2-score) pairs for this 2-row group
    float* __restrict__ op,              // out + row0*M + tx
    const float4* __restrict__ tb,       // tboxes + tx
    const int* __restrict__ lp,          // lraw + (tx << SH)
    const unsigned long long nqc[2],     // packed (-qcx, -qcy) per row
    const float qwz[2], const float qwh[2],
    const float qx0[2], const float qy0[2],
    const float qx1[2], const float qy1[2])
{
    constexpr int M = 1280;

#pragma unroll 10
    for (int jj = 0; jj < 20; jj++) {
        float4 b = __ldg(tb + jj * 64);          // target cxcywh
        int lab = __ldg(lp + ((jj * 64) << SH)); // immediate-offset label
        float hw = 0.5f * b.z, hh = 0.5f * b.w;
        float tx0 = b.x - hw, ty0 = b.y - hh;
        float tx1 = b.x + hw, ty1 = b.y + hh;
        float ta = b.z * b.w;

        unsigned long long bxy;
        PACK2(bxy, b.x, b.y);                    // aligned pair from float4 -> free

        float2 sc2 = ssc2[lab];                  // one LDS.64: (2-sc) for both rows
        float scv[2] = {sc2.x, sc2.y};

#pragma unroll
        for (int k = 0; k < 2; k++) {
            // L1 on raw cxcywh: x/y diff via packed add (b + (-qc)); abs makes
            // the sign flip irrelevant. w/h diffs scalar.
            unsigned long long u;
            ADDX2(u, bxy, nqc[k]);
            float ux, uy;
            UNPACK2(ux, uy, u);
            float vx = qwz[k] - b.z, vy = qwh[k] - b.w;
            float l1 = (fabsf(ux) + fabsf(uy)) + (fabsf(vx) + fabsf(vy));

            // signed per-dim overlap, reused for intersection and enclosure
            float ox = fminf(qx1[k], tx1) - fmaxf(qx0[k], tx0);
            float oy = fminf(qy1[k], ty1) - fmaxf(qy0[k], ty0);
            float iw = fmaxf(ox, 0.0f), ih = fmaxf(oy, 0.0f);
            float inter = iw * ih;

            // enclosing span = w + w' - signed_overlap
            float ew = (qwz[k] + b.z) - ox;
            float eh = (qwh[k] + b.w) - oy;
            float ae = ew * eh;

            float uni = fmaf(qwz[k], qwh[k], ta) - inter;

            // cost = 5*l1 + (2 - sc) - 2*(inter/uni + uni/ae); (2-sc) pre-staged
            float s = fmaf(uni, frcp(ae), inter * frcp(uni));
            float c = fmaf(5.0f, l1, scv[k]);
            c = fmaf(-2.0f, s, c);

            op[k * M + jj * 64] = c;
        }
    }
}

// ---------------------------------------------------------------------------
// Fast path: C=91, M=1280, rows % 8 == 0. Single launch. R12 geometry:
// 256-thr block = 4 groups x (2 rows x 64 lanes) = 8 rows; grid = rows/8;
// launch_bounds(256,5) -> 48-reg cap, 40 warps/SM.
// Staging: warp w=(2g+r) writes row (8*bid+2g+r) as (2 - score) into the
// group-g interleaved array s_sc[g][c][r], so the inner loop needs one
// LDS.64 per column step for both rows.
// ---------------------------------------------------------------------------
__global__ void __launch_bounds__(256, 5)
cost_kernel_fast(const float* __restrict__ scores,
                 const float4* __restrict__ boxes,
                 const int* __restrict__ lraw,
                 const float4* __restrict__ tboxes,
                 float* __restrict__ out) {
    constexpr int C = 91;
    constexpr int M = 1280;

    __shared__ float s_sc[4 * C * 2];   // [group][col][row-in-pair]
    __shared__ int s_is64;

    int tid = threadIdx.x;
    int tx = tid & 63;
    int ty = tid >> 6;
    int row0 = blockIdx.x * 8 + ty * 2;

    if (tid == 0) s_is64 = 1;
    __syncthreads();

    // Label-width probe: int64 labels (<2^31) have all-zero high words.
    {
        int any = 0;
#pragma unroll 1
        for (int t = tid; t < M / 2; t += 256)
            any |= lraw[2 * t + 1];
        if (any != 0) s_is64 = 0;
    }

    // Stage 8 score rows pre-negated and row-pair interleaved.
    {
        int w = tid >> 5, l = tid & 31;
        int g = w >> 1, r = w & 1;
        const float* src = scores + (size_t)(blockIdx.x * 8 + g * 2 + r) * C;
#pragma unroll
        for (int c = l; c < C; c += 32)
            s_sc[g * (C * 2) + c * 2 + r] = 2.0f - __ldg(src + c);
    }

    unsigned long long nqc[2];
    float qwz[2], qwh[2];
    float qx0[2], qy0[2], qx1[2], qy1[2];
#pragma unroll
    for (int k = 0; k < 2; k++) {
        float4 bb = __ldg(boxes + row0 + k);
        PACK2(nqc[k], -bb.x, -bb.y);
        qwz[k] = bb.z; qwh[k] = bb.w;
        float hw = 0.5f * bb.z, hh = 0.5f * bb.w;
        qx0[k] = bb.x - hw; qy0[k] = bb.y - hh;
        qx1[k] = bb.x + hw; qy1[k] = bb.y + hh;
    }
    __syncthreads();

    const float2* ssc2 = reinterpret_cast<const float2*>(s_sc + ty * (C * 2));
    float* op = out + (size_t)row0 * M + tx;
    const float4* tb = tboxes + tx;

    if (s_is64)
        cost_tile2<1>(ssc2, op, tb, lraw + 2 * tx,
                      nqc, qwz, qwh, qx0, qy0, qx1, qy1);
    else
        cost_tile2<0>(ssc2, op, tb, lraw + tx,
                      nqc, qwz, qwh, qx0, qy0, qx1, qy1);
}

// ---------------------------------------------------------------------------
// Generic fallback for unexpected shapes.
// ---------------------------------------------------------------------------
__global__ void __launch_bounds__(256)
cost_kernel(const float* __restrict__ scores,
            const float4* __restrict__ boxes,
            const float4* __restrict__ tboxes,
            float* __restrict__ out,
            int rows, int C, int m) {
    int tid = threadIdx.x;
    int tx = tid & 63;
    int ty = tid >> 6;
    int row0 = blockIdx.x * 16 + ty * 4;

    float qcx[4], qcy[4], qw[4], qh[4];
    float qx0[4], qy0[4], qx1[4], qy1[4], qa[4];
    const float* srow[4];
    float* orow[4];

#pragma unroll
    for (int k = 0; k < 4; k++) {
        int r = row0 + k;
        if (r > rows - 1) r = rows - 1;
        float4 bb = __ldg(boxes + r);
        qcx[k] = bb.x; qcy[k] = bb.y; qw[k] = bb.z; qh[k] = bb.w;
        float hw = 0.5f * bb.z, hh = 0.5f * bb.w;
        qx0[k] = bb.x - hw; qy0[k] = bb.y - hh;
        qx1[k] = bb.x + hw; qy1[k] = bb.y + hh;
        qa[k] = (qx1[k] - qx0[k]) * (qy1[k] - qy0[k]);
        srow[k] = scores + (size_t)r * C;
        orow[k] = out + (size_t)r * m + tx;
    }

    int nj = (m + 63) >> 6;
    for (int jj = 0; jj < nj; jj++) {
        int j = tx + (jj << 6);
        if (j >= m) break;
        float4 t  = __ldg(g_txyxy + j);
        float4 tc = __ldg(tboxes + j);
        float2 al = __ldg(g_tal + j);
        float ta = al.x;
        int lab = __float_as_int(al.y);

#pragma unroll
        for (int k = 0; k < 4; k++) {
            float sc = __ldg(srow[k] + lab);
            float l1 = fabsf(qcx[k] - tc.x) + fabsf(qcy[k] - tc.y)
                     + fabsf(qw[k] - tc.z) + fabsf(qh[k] - tc.w);
            float ltx = fmaxf(qx0[k], t.x), lty = fmaxf(qy0[k], t.y);
            float rbx = fminf(qx1[k], t.z), rby = fminf(qy1[k], t.w);
            float iw = fmaxf(rbx - ltx, 0.0f), ih = fmaxf(rby - lty, 0.0f);
            float inter = iw * ih;
            float uni = qa[k] + ta - inter;
            float ex0 = fminf(qx0[k], t.x), ey0 = fminf(qy0[k], t.y);
            float ex1 = fmaxf(qx1[k], t.z), ey1 = fmaxf(qy1[k], t.w);
            float ae = (ex1 - ex0) * (ey1 - ey0);
            float s = fmaf(uni, frcp(ae), inter * frcp(uni));
            float c = fmaf(5.0f, l1, 2.0f - sc);
            c = fmaf(-2.0f, s, c);
            orow[k][(size_t)(jj << 6)] = c;
        }
    }
}

extern "C" void kernel_launch(void* const* d_in, const int* in_sizes, int n_in,
                              void* d_out, int out_size) {
    const float* scores  = (const float*)d_in[0];
    const float4* boxes  = (const float4*)d_in[1];
    const int*   labraw  = (const int*)d_in[2];
    const float4* tboxes = (const float4*)d_in[3];
    float* out = (float*)d_out;

    int rows = in_sizes[1] / 4;      // b*n = 9600
    int m    = in_sizes[3] / 4;      // 1280
    int C    = in_sizes[0] / rows;   // 91

    if (C == 91 && m == 1280 && (rows % 8) == 0) {
        cost_kernel_fast<<<rows / 8, 256>>>(scores, boxes, labraw, tboxes, out);
    } else {
        setup_kernel<<<1, 512>>>(tboxes, labraw, m);
        int blocks = (rows + 15) / 16;
        cost_kernel<<<blocks, 256>>>(scores, boxes, tboxes, out, rows, C, m);
    }
}

// round 14
// speedup vs baseline: 1.2033x; 1.0541x over previous
#include <cuda_runtime.h>
#include <cstdint>

#define TMAX 1280

__device__ int g_lab[TMAX];        // fallback path only
__device__ float4 g_txyxy[TMAX];   // fallback path only
__device__ float2 g_tal[TMAX];     // fallback path only

__device__ __forceinline__ float frcp(float x) {
    float r;
    asm("rcp.approx.f32 %0, %1;" : "=f"(r) : "f"(x));
    return r;
}

// Packed f32x2 helpers (bit-exact per-lane .rn arithmetic; sm_100a).
#define PACK2(dst, lo, hi) \
    asm("mov.b64 %0, {%1, %2};" : "=l"(dst) : "r"(__float_as_uint(lo)), "r"(__float_as_uint(hi)))
#define UNPACK2(lo, hi, src) do { unsigned int _ulo, _uhi; \
    asm("mov.b64 {%0, %1}, %2;" : "=r"(_ulo), "=r"(_uhi) : "l"(src)); \
    lo = __uint_as_float(_ulo); hi = __uint_as_float(_uhi); } while (0)
#define ADDX2(dst, a, b) \
    asm("add.rn.f32x2 %0, %1, %2;" : "=l"(dst) : "l"(a), "l"(b))
#define FMAX2(dst, a, b, c) \
    asm("fma.rn.f32x2 %0, %1, %2, %3;" : "=l"(dst) : "l"(a), "l"(b), "l"(c))

// Fallback-path setup: label normalize + target xyxy/area precompute.
__global__ void setup_kernel(const float4* __restrict__ tboxes,
                             const int* __restrict__ lraw, int m) {
    __shared__ int is64;
    if (threadIdx.x == 0) is64 = 1;
    __syncthreads();
    for (int t = threadIdx.x; t < m / 2; t += blockDim.x)
        if (lraw[2 * t + 1] != 0) is64 = 0;
    __syncthreads();
    int f = is64;
    for (int j = threadIdx.x; j < m; j += blockDim.x) {
        int lab = f ? lraw[2 * j] : lraw[j];
        g_lab[j] = lab;
        float4 b = tboxes[j];
        float hw = 0.5f * b.z, hh = 0.5f * b.w;
        float4 t;
        t.x = b.x - hw; t.y = b.y - hh;
        t.z = b.x + hw; t.w = b.y + hh;
        g_txyxy[j] = t;
        float2 al;
        al.x = (t.z - t.x) * (t.w - t.y);
        al.y = __int_as_float(lab);
        g_tal[j] = al;
    }
}

// ---------------------------------------------------------------------------
// Fast-path tile body: 2 rows x 20 column steps per thread (R7 geometry),
// min/max-free formulation:
//   d0 = t0 - q0, d1 = t1 - q1 (packed, sign-flipped; all consumers abs-fold)
//   a  = |d1| + |d0| per dim
//   overlap  ox = hsw - a/2   (FFMA-imm)     hsw = qw/2 + tw/2
//   enclose  ew = hsw + a/2   (FFMA-imm)
//   L1: |dcx|+|dcy| = |d0+d1|/2 (packed add), |dw|+|dh| = 2(|qw/2 - tw/2|...)
//   cost = 2.5*sA + 10*sB + (2 - sc) - 2*(inter/uni + uni/ae)
// Templated on label stride (SH=1: int64 source, SH=0: int32).
// ---------------------------------------------------------------------------
template <int SH>
__device__ __forceinline__ void cost_tile2(
    const float2* __restrict__ ssc2,     // smem (2-score) pairs for this 2-row group
    float* __restrict__ op,              // out + row0*M + tx
    const float4* __restrict__ tb,       // tboxes + tx
    const int* __restrict__ lp,          // lraw + (tx << SH)
    const unsigned long long nq0[2],     // packed (-qx0, -qy0)
    const unsigned long long nq1[2],     // packed (-qx1, -qy1)
    const float hqwx[2], const float hqwy[2],  // qw/2, qh/2
    const float qa[2])                   // qw*qh
{
    constexpr int M = 1280;

    unsigned long long PH, NH;
    PACK2(PH, 0.5f, 0.5f);
    PACK2(NH, -0.5f, -0.5f);

#pragma unroll 10
    for (int jj = 0; jj < 20; jj++) {
        float4 b = __ldg(tb + jj * 64);          // target cxcywh
        int lab = __ldg(lp + ((jj * 64) << SH)); // immediate-offset label

        unsigned long long bxy, bwh, t0, t1;
        PACK2(bxy, b.x, b.y);
        PACK2(bwh, b.z, b.w);
        FMAX2(t0, bwh, NH, bxy);                 // (tx0, ty0)
        FMAX2(t1, bwh, PH, bxy);                 // (tx1, ty1)
        float ta = b.z * b.w;
        float htwx = 0.5f * b.z, htwy = 0.5f * b.w;

        float2 sc2 = ssc2[lab];                  // one LDS.64: (2-sc) for both rows
        float scv[2] = {sc2.x, sc2.y};

#pragma unroll
        for (int k = 0; k < 2; k++) {
            unsigned long long d0, d1, sA2;
            ADDX2(d0, t0, nq0[k]);               // (tx0-qx0, ty0-qy0)
            ADDX2(d1, t1, nq1[k]);               // (tx1-qx1, ty1-qy1)
            ADDX2(sA2, d0, d1);                  // 2*(tc - qc) per dim

            float d0x, d0y, d1x, d1y, sax, say;
            UNPACK2(d0x, d0y, d0);
            UNPACK2(d1x, d1y, d1);
            UNPACK2(sax, say, sA2);

            float ax = fabsf(d1x) + fabsf(d0x);
            float ay = fabsf(d1y) + fabsf(d0y);
            float sAs = fabsf(sax) + fabsf(say); // 2*(|dcx|+|dcy|)

            float hswx = hqwx[k] + htwx;         // (qw+tw)/2
            float hswy = hqwy[k] + htwy;
            float vx = hqwx[k] - htwx;           // (qw-tw)/2
            float vy = hqwy[k] - htwy;
            float sB = fabsf(vx) + fabsf(vy);    // (|dw|+|dh|)/2

            float ox = fmaf(ax, -0.5f, hswx);    // min(hi)-max(lo), signed
            float oy = fmaf(ay, -0.5f, hswy);
            float ewx = fmaf(ax, 0.5f, hswx);    // enclosing span
            float ewy = fmaf(ay, 0.5f, hswy);

            float iw = fmaxf(ox, 0.0f), ih = fmaxf(oy, 0.0f);
            float inter = iw * ih;
            float ae = ewx * ewy;
            float uni = (qa[k] + ta) - inter;

            float s = fmaf(uni, frcp(ae), inter * frcp(uni));
            float c = fmaf(sAs, 2.5f, scv[k]);   // 5 * (|dcx|+|dcy|)
            c = fmaf(sB, 10.0f, c);              // 5 * (|dw|+|dh|)
            c = fmaf(-2.0f, s, c);

            op[k * M + jj * 64] = c;
        }
    }
}

// ---------------------------------------------------------------------------
// Fast path: C=91, M=1280, rows % 8 == 0. Single launch. R12/R13 geometry:
// 256-thr block = 4 groups x (2 rows x 64 lanes) = 8 rows; grid = rows/8;
// launch_bounds(256,5) -> 51-reg cap, 40 warps/SM. Interleaved (2-score)
// staging unchanged from R13.
// ---------------------------------------------------------------------------
__global__ void __launch_bounds__(256, 5)
cost_kernel_fast(const float* __restrict__ scores,
                 const float4* __restrict__ boxes,
                 const int* __restrict__ lraw,
                 const float4* __restrict__ tboxes,
                 float* __restrict__ out) {
    constexpr int C = 91;
    constexpr int M = 1280;

    __shared__ float s_sc[4 * C * 2];   // [group][col][row-in-pair]
    __shared__ int s_is64;

    int tid = threadIdx.x;
    int tx = tid & 63;
    int ty = tid >> 6;
    int row0 = blockIdx.x * 8 + ty * 2;

    if (tid == 0) s_is64 = 1;
    __syncthreads();

    // Label-width probe: int64 labels (<2^31) have all-zero high words.
    {
        int any = 0;
#pragma unroll 1
        for (int t = tid; t < M / 2; t += 256)
            any |= lraw[2 * t + 1];
        if (any != 0) s_is64 = 0;
    }

    // Stage 8 score rows pre-negated and row-pair interleaved.
    {
        int w = tid >> 5, l = tid & 31;
        int g = w >> 1, r = w & 1;
        const float* src = scores + (size_t)(blockIdx.x * 8 + g * 2 + r) * C;
#pragma unroll
        for (int c = l; c < C; c += 32)
            s_sc[g * (C * 2) + c * 2 + r] = 2.0f - __ldg(src + c);
    }

    unsigned long long nq0[2], nq1[2];
    float hqwx[2], hqwy[2], qa[2];
#pragma unroll
    for (int k = 0; k < 2; k++) {
        float4 bb = __ldg(boxes + row0 + k);
        float hw = 0.5f * bb.z, hh = 0.5f * bb.w;
        float qx0 = bb.x - hw, qy0 = bb.y - hh;
        float qx1 = bb.x + hw, qy1 = bb.y + hh;
        PACK2(nq0[k], -qx0, -qy0);
        PACK2(nq1[k], -qx1, -qy1);
        hqwx[k] = hw; hqwy[k] = hh;
        qa[k] = bb.z * bb.w;
    }
    __syncthreads();

    const float2* ssc2 = reinterpret_cast<const float2*>(s_sc + ty * (C * 2));
    float* op = out + (size_t)row0 * M + tx;
    const float4* tb = tboxes + tx;

    if (s_is64)
        cost_tile2<1>(ssc2, op, tb, lraw + 2 * tx,
                      nq0, nq1, hqwx, hqwy, qa);
    else
        cost_tile2<0>(ssc2, op, tb, lraw + tx,
                      nq0, nq1, hqwx, hqwy, qa);
}

// ---------------------------------------------------------------------------
// Generic fallback for unexpected shapes.
// ---------------------------------------------------------------------------
__global__ void __launch_bounds__(256)
cost_kernel(const float* __restrict__ scores,
            const float4* __restrict__ boxes,
            const float4* __restrict__ tboxes,
            float* __restrict__ out,
            int rows, int C, int m) {
    int tid = threadIdx.x;
    int tx = tid & 63;
    int ty = tid >> 6;
    int row0 = blockIdx.x * 16 + ty * 4;

    float qcx[4], qcy[4], qw[4], qh[4];
    float qx0[4], qy0[4], qx1[4], qy1[4], qa[4];
    const float* srow[4];
    float* orow[4];

#pragma unroll
    for (int k = 0; k < 4; k++) {
        int r = row0 + k;
        if (r > rows - 1) r = rows - 1;
        float4 bb = __ldg(boxes + r);
        qcx[k] = bb.x; qcy[k] = bb.y; qw[k] = bb.z; qh[k] = bb.w;
        float hw = 0.5f * bb.z, hh = 0.5f * bb.w;
        qx0[k] = bb.x - hw; qy0[k] = bb.y - hh;
        qx1[k] = bb.x + hw; qy1[k] = bb.y + hh;
        qa[k] = (qx1[k] - qx0[k]) * (qy1[k] - qy0[k]);
        srow[k] = scores + (size_t)r * C;
        orow[k] = out + (size_t)r * m + tx;
    }

    int nj = (m + 63) >> 6;
    for (int jj = 0; jj < nj; jj++) {
        int j = tx + (jj << 6);
        if (j >= m) break;
        float4 t  = __ldg(g_txyxy + j);
        float4 tc = __ldg(tboxes + j);
        float2 al = __ldg(g_tal + j);
        float ta = al.x;
        int lab = __float_as_int(al.y);

#pragma unroll
        for (int k = 0; k < 4; k++) {
            float sc = __ldg(srow[k] + lab);
            float l1 = fabsf(qcx[k] - tc.x) + fabsf(qcy[k] - tc.y)
                     + fabsf(qw[k] - tc.z) + fabsf(qh[k] - tc.w);
            float ltx = fmaxf(qx0[k], t.x), lty = fmaxf(qy0[k], t.y);
            float rbx = fminf(qx1[k], t.z), rby = fminf(qy1[k], t.w);
            float iw = fmaxf(rbx - ltx, 0.0f), ih = fmaxf(rby - lty, 0.0f);
            float inter = iw * ih;
            float uni = qa[k] + ta - inter;
            float ex0 = fminf(qx0[k], t.x), ey0 = fminf(qy0[k], t.y);
            float ex1 = fmaxf(qx1[k], t.z), ey1 = fmaxf(qy1[k], t.w);
            float ae = (ex1 - ex0) * (ey1 - ey0);
            float s = fmaf(uni, frcp(ae), inter * frcp(uni));
            float c = fmaf(5.0f, l1, 2.0f - sc);
            c = fmaf(-2.0f, s, c);
            orow[k][(size_t)(jj << 6)] = c;
        }
    }
}

extern "C" void kernel_launch(void* const* d_in, const int* in_sizes, int n_in,
                              void* d_out, int out_size) {
    const float* scores  = (const float*)d_in[0];
    const float4* boxes  = (const float4*)d_in[1];
    const int*   labraw  = (const int*)d_in[2];
    const float4* tboxes = (const float4*)d_in[3];
    float* out = (float*)d_out;

    int rows = in_sizes[1] / 4;      // b*n = 9600
    int m    = in_sizes[3] / 4;      // 1280
    int C    = in_sizes[0] / rows;   // 91

    if (C == 91 && m == 1280 && (rows % 8) == 0) {
        cost_kernel_fast<<<rows / 8, 256>>>(scores, boxes, labraw, tboxes, out);
    } else {
        setup_kernel<<<1, 512>>>(tboxes, labraw, m);
        int blocks = (rows + 15) / 16;
        cost_kernel<<<blocks, 256>>>(scores, boxes, tboxes, out, rows, C, m);
    }
}